// round 15
// baseline (speedup 1.0000x reference)
#include <cuda_runtime.h>
#include <cuda_bf16.h>

#define B    8
#define C    256
#define HW4  16384                 // float4 per (b,c) plane
#define F4_PER_BLOCK  1024         // 4 float4/thread * 256 threads
#define BLOCKS_PER_PLANE (HW4 / F4_PER_BLOCK)        // 16

// Scratch (no allocation allowed -> __device__ globals)
__device__ float g_h[B * C];        // hidden layer
__device__ float g_logits[B * C];   // logits

// ---------------------------------------------------------------------------
// Warp-per-CHANNEL matvec over all 8 batches: each warp loads its weight row
// ONCE (2 float4/lane), then loops batches (input rows are tiny + L2-hot):
//   out[b,c] = act( in[b,:] . W[c,:] + bias[c] )   for b = 0..7
// 32 blocks x 256 threads = 256 warps = C channels. Weight matrix read once.
// ---------------------------------------------------------------------------
template <bool LEAKY>
__global__ void __launch_bounds__(256) matvec_kernel(const float* __restrict__ in,
                                                     const float* __restrict__ W,
                                                     const float* __restrict__ bias,
                                                     float* __restrict__ out) {
    const int c    = blockIdx.x * 8 + (threadIdx.x >> 5);   // 0..255
    const int lane = threadIdx.x & 31;

    const float4* __restrict__ w4 = (const float4*)(W + c * C);
    const float4 wa = __ldg(w4 + lane);
    const float4 wb = __ldg(w4 + lane + 32);
    const float bia = __ldg(bias + c);

    #pragma unroll
    for (int b = 0; b < B; ++b) {
        const float4* __restrict__ i4 = (const float4*)(in + b * C);
        const float4 ia = __ldg(i4 + lane);
        const float4 ib = __ldg(i4 + lane + 32);

        float p = wa.x*ia.x + wa.y*ia.y + wa.z*ia.z + wa.w*ia.w
                + wb.x*ib.x + wb.y*ib.y + wb.z*ib.z + wb.w*ib.w;

        #pragma unroll
        for (int s = 16; s > 0; s >>= 1)
            p += __shfl_xor_sync(0xffffffffu, p, s);

        if (lane == 0) {
            float r = p + bia;
            if (LEAKY) r = r > 0.0f ? r : 0.1f * r;
            out[b * C + c] = r;
        }
    }
}

// ---------------------------------------------------------------------------
// Stream + in-preamble softmax (R13 winner, byte-identical stream body).
// Warp 0 recomputes the row softmax from the L2-resident logits, derives
// s = 1 + e_chan/sum, broadcasts via smem; then the proven 4xfloat4 stream.
// ---------------------------------------------------------------------------
__global__ void __launch_bounds__(256) scale_kernel(const float4* __restrict__ x,
                                                    float4* __restrict__ y) {
    const int blk   = blockIdx.x;
    const int plane = blk >> 4;                 // b*C + c
    __shared__ float s_scale;

    if (threadIdx.x < 32) {
        const int lane = threadIdx.x;
        const int brow = plane >> 8;
        const int chan = plane & 255;
        const float* __restrict__ lrow = g_logits + brow * C;

        float l0 = __ldg(lrow + lane);
        float l1 = __ldg(lrow + lane + 32);
        float l2 = __ldg(lrow + lane + 64);
        float l3 = __ldg(lrow + lane + 96);
        float l4 = __ldg(lrow + lane + 128);
        float l5 = __ldg(lrow + lane + 160);
        float l6 = __ldg(lrow + lane + 192);
        float l7 = __ldg(lrow + lane + 224);

        float m = fmaxf(fmaxf(fmaxf(l0, l1), fmaxf(l2, l3)),
                        fmaxf(fmaxf(l4, l5), fmaxf(l6, l7)));
        #pragma unroll
        for (int s = 16; s > 0; s >>= 1)
            m = fmaxf(m, __shfl_xor_sync(0xffffffffu, m, s));

        float t = __expf(l0 - m) + __expf(l1 - m) + __expf(l2 - m) + __expf(l3 - m)
                + __expf(l4 - m) + __expf(l5 - m) + __expf(l6 - m) + __expf(l7 - m);
        #pragma unroll
        for (int s = 16; s > 0; s >>= 1)
            t += __shfl_xor_sync(0xffffffffu, t, s);

        if (lane == 0) {
            const float myl = __ldg(lrow + chan);
            s_scale = 1.0f + __expf(myl - m) / t;
        }
    }
    __syncthreads();
    const float s = s_scale;

    const size_t i0 = (size_t)blk * F4_PER_BLOCK + threadIdx.x;

    float4 v0 = __ldcs(x + i0);
    float4 v1 = __ldcs(x + i0 + 256);
    float4 v2 = __ldcs(x + i0 + 512);
    float4 v3 = __ldcs(x + i0 + 768);

    v0.x *= s; v0.y *= s; v0.z *= s; v0.w *= s;
    v1.x *= s; v1.y *= s; v1.z *= s; v1.w *= s;
    v2.x *= s; v2.y *= s; v2.z *= s; v2.w *= s;
    v3.x *= s; v3.y *= s; v3.z *= s; v3.w *= s;

    __stcs(y + i0,       v0);
    __stcs(y + i0 + 256, v1);
    __stcs(y + i0 + 512, v2);
    __stcs(y + i0 + 768, v3);
}

extern "C" void kernel_launch(void* const* d_in, const int* in_sizes, int n_in,
                              void* d_out, int out_size) {
    const float* x        = (const float*)d_in[0];
    const float* semantic = (const float*)d_in[1];
    const float* W1       = (const float*)d_in[2];
    const float* b1       = (const float*)d_in[3];
    const float* W2       = (const float*)d_in[4];
    const float* b2       = (const float*)d_in[5];
    float* out = (float*)d_out;

    float *g_h_ptr, *g_logits_ptr;
    cudaGetSymbolAddress((void**)&g_h_ptr, g_h);
    cudaGetSymbolAddress((void**)&g_logits_ptr, g_logits);

    matvec_kernel<true ><<<32, 256>>>(semantic, W1, b1, g_h_ptr);
    matvec_kernel<false><<<32, 256>>>(g_h_ptr, W2, b2, g_logits_ptr);

    const int nblocks = (B * C) * BLOCKS_PER_PLANE;   // 32768
    scale_kernel<<<nblocks, 256>>>((const float4*)x, (float4*)out);
}

// round 16
// speedup vs baseline: 1.0111x; 1.0111x over previous
#include <cuda_runtime.h>
#include <cuda_bf16.h>

#define B    8
#define C    256
#define HW4  16384                 // float4 per (b,c) plane
#define F4_PER_BLOCK  1024         // 4 float4/thread * 256 threads
#define BLOCKS_PER_PLANE (HW4 / F4_PER_BLOCK)        // 16

// Scratch (no allocation allowed -> __device__ globals)
__device__ float g_h[B * C];        // hidden layer
__device__ float g_logits[B * C];   // logits

// ---------------------------------------------------------------------------
// Warp-per-output matvec: out[b,c] = act( in[b,:] . W[c,:] + bias[c] )
// 256 blocks x 256 threads = 2048 warps = B*C outputs. Coalesced float4 rows.
// Maximum parallelism wins over read de-duplication for this latency-bound
// kernel (R15 falsified the alternative).
// ---------------------------------------------------------------------------
template <bool LEAKY>
__global__ void __launch_bounds__(256) matvec_kernel(const float* __restrict__ in,
                                                     const float* __restrict__ W,
                                                     const float* __restrict__ bias,
                                                     float* __restrict__ out) {
    const int warp = (blockIdx.x * blockDim.x + threadIdx.x) >> 5; // 0..2047
    const int lane = threadIdx.x & 31;
    const int b = warp >> 8;        // 0..7
    const int c = warp & 255;       // 0..255

    const float4* __restrict__ w4 = (const float4*)(W + c * C);
    const float4* __restrict__ i4 = (const float4*)(in + b * C);

    float4 wa = __ldg(w4 + lane);
    float4 wb = __ldg(w4 + lane + 32);
    float4 ia = __ldg(i4 + lane);
    float4 ib = __ldg(i4 + lane + 32);

    float p = wa.x * ia.x + wa.y * ia.y + wa.z * ia.z + wa.w * ia.w
            + wb.x * ib.x + wb.y * ib.y + wb.z * ib.z + wb.w * ib.w;

    #pragma unroll
    for (int s = 16; s > 0; s >>= 1)
        p += __shfl_xor_sync(0xffffffffu, p, s);

    if (lane == 0) {
        float r = p + __ldg(bias + c);
        if (LEAKY) r = r > 0.0f ? r : 0.1f * r;
        out[b * C + c] = r;
    }
}

// ---------------------------------------------------------------------------
// Stream + in-preamble softmax. Warp 0 recomputes the row softmax from the
// L2-resident logits (8 coalesced loads/lane + shuffle reductions), derives
// s = 1 + e_chan / sum, broadcasts via smem. Preamble hides under the
// 28-deep wave oversubscription. Then the proven 4xfloat4 stream:
// front-batched loads (MLP_p1=4), streaming ld/st hints (touch-once data).
// ---------------------------------------------------------------------------
__global__ void __launch_bounds__(256) scale_kernel(const float4* __restrict__ x,
                                                    float4* __restrict__ y) {
    const int blk   = blockIdx.x;
    const int plane = blk >> 4;                 // b*C + c
    __shared__ float s_scale;

    if (threadIdx.x < 32) {
        const int lane = threadIdx.x;
        const int brow = plane >> 8;
        const int chan = plane & 255;
        const float* __restrict__ lrow = g_logits + brow * C;

        float l0 = __ldg(lrow + lane);
        float l1 = __ldg(lrow + lane + 32);
        float l2 = __ldg(lrow + lane + 64);
        float l3 = __ldg(lrow + lane + 96);
        float l4 = __ldg(lrow + lane + 128);
        float l5 = __ldg(lrow + lane + 160);
        float l6 = __ldg(lrow + lane + 192);
        float l7 = __ldg(lrow + lane + 224);

        float m = fmaxf(fmaxf(fmaxf(l0, l1), fmaxf(l2, l3)),
                        fmaxf(fmaxf(l4, l5), fmaxf(l6, l7)));
        #pragma unroll
        for (int s = 16; s > 0; s >>= 1)
            m = fmaxf(m, __shfl_xor_sync(0xffffffffu, m, s));

        float t = __expf(l0 - m) + __expf(l1 - m) + __expf(l2 - m) + __expf(l3 - m)
                + __expf(l4 - m) + __expf(l5 - m) + __expf(l6 - m) + __expf(l7 - m);
        #pragma unroll
        for (int s = 16; s > 0; s >>= 1)
            t += __shfl_xor_sync(0xffffffffu, t, s);

        if (lane == 0) {
            const float myl = __ldg(lrow + chan);
            s_scale = 1.0f + __expf(myl - m) / t;
        }
    }
    __syncthreads();
    const float s = s_scale;

    const size_t i0 = (size_t)blk * F4_PER_BLOCK + threadIdx.x;

    float4 v0 = __ldcs(x + i0);
    float4 v1 = __ldcs(x + i0 + 256);
    float4 v2 = __ldcs(x + i0 + 512);
    float4 v3 = __ldcs(x + i0 + 768);

    v0.x *= s; v0.y *= s; v0.z *= s; v0.w *= s;
    v1.x *= s; v1.y *= s; v1.z *= s; v1.w *= s;
    v2.x *= s; v2.y *= s; v2.z *= s; v2.w *= s;
    v3.x *= s; v3.y *= s; v3.z *= s; v3.w *= s;

    __stcs(y + i0,       v0);
    __stcs(y + i0 + 256, v1);
    __stcs(y + i0 + 512, v2);
    __stcs(y + i0 + 768, v3);
}

extern "C" void kernel_launch(void* const* d_in, const int* in_sizes, int n_in,
                              void* d_out, int out_size) {
    const float* x        = (const float*)d_in[0];
    const float* semantic = (const float*)d_in[1];
    const float* W1       = (const float*)d_in[2];
    const float* b1       = (const float*)d_in[3];
    const float* W2       = (const float*)d_in[4];
    const float* b2       = (const float*)d_in[5];
    float* out = (float*)d_out;

    float *g_h_ptr, *g_logits_ptr;
    cudaGetSymbolAddress((void**)&g_h_ptr, g_h);
    cudaGetSymbolAddress((void**)&g_logits_ptr, g_logits);

    matvec_kernel<true ><<<256, 256>>>(semantic, W1, b1, g_h_ptr);
    matvec_kernel<false><<<256, 256>>>(g_h_ptr, W2, b2, g_logits_ptr);

    const int nblocks = (B * C) * BLOCKS_PER_PLANE;   // 32768
    scale_kernel<<<nblocks, 256>>>((const float4*)x, (float4*)out);
}